// round 3
// baseline (speedup 1.0000x reference)
#include <cuda_runtime.h>
#include <cuda_fp16.h>

#define NN 100000
#define EE 3200000
#define ETOT (EE + NN)
#define AGG_GRID 1184
#define FULLM 0xffffffffu

// ---- device scratch ----
__device__ __half2 g_hA[NN * 32];
__device__ __half2 g_hC[NN * 32];
__device__ float2  g_asc1[NN], g_adc1[NN];
__device__ float2  g_asc2[NN], g_adc2[NN];
__device__ float   g_asc3[NN], g_adc3[NN];
__device__ float4  g_h3[NN];
__device__ int     g_cnt[NN];          // zero-init; scatter drains back to 0
__device__ int     g_rowptr[NN + 1];
__device__ int     g_csr[ETOT];
__device__ int     g_bsum[128];

// ============================ CSR build ============================

__global__ void k_hist(const int* __restrict__ ei) {
    int i = blockIdx.x * blockDim.x + threadIdx.x;
    if (i >= ETOT) return;
    int dst = (i < EE) ? ei[EE + i] : (i - EE);
    atomicAdd(&g_cnt[dst], 1);
}

__global__ void k_scan1() {
    __shared__ int sd[1024];
    int t = threadIdx.x;
    int i = blockIdx.x * 1024 + t;
    int v = (i < NN) ? g_cnt[i] : 0;
    sd[t] = v;
    __syncthreads();
    #pragma unroll
    for (int o = 1; o < 1024; o <<= 1) {
        int a = (t >= o) ? sd[t - o] : 0;
        __syncthreads();
        sd[t] += a;
        __syncthreads();
    }
    if (i < NN) g_rowptr[i] = sd[t] - v;          // exclusive within block
    if (t == 1023) g_bsum[blockIdx.x] = sd[1023];
}

// fused: per-block offset (sum of earlier block totals) + add to rowptr
__global__ void k_scan23() {
    __shared__ int off;
    int b = blockIdx.x, t = threadIdx.x;
    if (t < 32) {
        int acc = 0;
        for (int j = t; j < b; j += 32) acc += g_bsum[j];
        #pragma unroll
        for (int o = 16; o >= 1; o >>= 1) acc += __shfl_xor_sync(FULLM, acc, o);
        if (t == 0) off = acc;
    }
    __syncthreads();
    int i = b * 1024 + t;
    if (i < NN) g_rowptr[i] += off;
    if (b == gridDim.x - 1 && t == 0) g_rowptr[NN] = off + g_bsum[b];
}

__global__ void k_scatter(const int* __restrict__ ei) {
    int i = blockIdx.x * blockDim.x + threadIdx.x;
    if (i >= ETOT) return;
    int src, dst;
    if (i < EE) { src = ei[i]; dst = ei[EE + i]; }
    else        { src = i - EE; dst = i - EE; }
    int pos = atomicSub(&g_cnt[dst], 1) - 1;      // drains g_cnt to 0
    g_csr[g_rowptr[dst] + pos] = src;
}

// ======================= layer 1: GEMM + logits ====================

__global__ void __launch_bounds__(256) k_gemm1(const float* __restrict__ x,
                                               const float* __restrict__ W,
                                               const float* __restrict__ as_,
                                               const float* __restrict__ ad_) {
    __shared__ float Ws[640];
    int t = threadIdx.x;
    for (int i = t; i < 640; i += 256) Ws[i] = W[i];
    __syncthreads();
    int lane = t & 31, w = t >> 5;
    int warpsTotal = gridDim.x * 8;
    for (int node = blockIdx.x * 8 + w; node < NN; node += warpsTotal) {
        float a0 = 0.f, a1 = 0.f;
        #pragma unroll
        for (int k = 0; k < 10; k++) {
            float xv = x[node * 10 + k];
            a0 = fmaf(xv, Ws[k * 64 + 2 * lane], a0);
            a1 = fmaf(xv, Ws[k * 64 + 2 * lane + 1], a1);
        }
        g_hA[node * 32 + lane] = __floats2half2_rn(a0, a1);
        float ps = a0 * as_[2 * lane] + a1 * as_[2 * lane + 1];
        float pd = a0 * ad_[2 * lane] + a1 * ad_[2 * lane + 1];
        #pragma unroll
        for (int o = 8; o >= 1; o >>= 1) {
            ps += __shfl_xor_sync(FULLM, ps, o);
            pd += __shfl_xor_sync(FULLM, pd, o);
        }
        float ps1 = __shfl_sync(FULLM, ps, 16);
        float pd1 = __shfl_sync(FULLM, pd, 16);
        if (lane == 0) {
            g_asc1[node] = make_float2(ps, ps1);
            g_adc1[node] = make_float2(pd, pd1);
        }
    }
}

// ================== edge-chunk helpers (register staged) ===========

__device__ __forceinline__ void stage_chunk(const float2* __restrict__ asc,
                                            float2 ad, int cb, int cnt, int lane,
                                            int& s, float& ex0, float& ex1) {
    s = 0; ex0 = 0.f; ex1 = 0.f;
    if (lane < cnt) {
        s = g_csr[cb + lane];
        float2 as = asc[s];
        float e0 = as.x + ad.x; e0 = (e0 > 0.f) ? e0 : 0.2f * e0;
        float e1 = as.y + ad.y; e1 = (e1 > 0.f) ? e1 : 0.2f * e1;
        ex0 = __expf(e0); ex1 = __expf(e1);
    }
}

__device__ __forceinline__ void consume32(const __half2* __restrict__ feat,
                                          int head, int lane,
                                          int cs, float ce0, float ce1,
                                          float& a0, float& a1) {
    #pragma unroll 8
    for (int j = 0; j < 32; j++) {
        int   ss = __shfl_sync(FULLM, cs, j);
        float eA = __shfl_sync(FULLM, ce0, j);
        float eB = __shfl_sync(FULLM, ce1, j);
        float exv = head ? eB : eA;
        float2 f = __half22float2(feat[ss * 32 + lane]);
        a0 = fmaf(exv, f.x, a0);
        a1 = fmaf(exv, f.y, a1);
    }
}

__device__ __forceinline__ void consume_tail(const __half2* __restrict__ feat,
                                             int head, int lane, int ccnt,
                                             int cs, float ce0, float ce1,
                                             float& a0, float& a1) {
    #pragma unroll 4
    for (int j = 0; j < ccnt; j++) {
        int   ss = __shfl_sync(FULLM, cs, j);
        float eA = __shfl_sync(FULLM, ce0, j);
        float eB = __shfl_sync(FULLM, ce1, j);
        float exv = head ? eB : eA;
        float2 f = __half22float2(feat[ss * 32 + lane]);
        a0 = fmaf(exv, f.x, a0);
        a1 = fmaf(exv, f.y, a1);
    }
}

// per-node softmax-weighted aggregation (64ch) with chunk pipelining
__device__ __forceinline__ void agg_node(const float2* __restrict__ asc,
                                         const __half2* __restrict__ feat,
                                         float2 ad, int beg, int end,
                                         int head, int lane,
                                         float& a0, float& a1, float& zout) {
    float z0 = 0.f, z1 = 0.f;
    a0 = 0.f; a1 = 0.f;
    int cb = beg;
    int cnt = min(32, end - cb);
    int s; float ex0, ex1;
    stage_chunk(asc, ad, cb, cnt, lane, s, ex0, ex1);
    z0 += ex0; z1 += ex1;
    while (true) {
        int ccnt = cnt, cs = s;
        float ce0 = ex0, ce1 = ex1;
        cb += 32;
        bool more = cb < end;
        if (more) {
            cnt = min(32, end - cb);
            stage_chunk(asc, ad, cb, cnt, lane, s, ex0, ex1);
            z0 += ex0; z1 += ex1;
        }
        if (ccnt == 32) consume32(feat, head, lane, cs, ce0, ce1, a0, a1);
        else            consume_tail(feat, head, lane, ccnt, cs, ce0, ce1, a0, a1);
        if (!more) break;
    }
    #pragma unroll
    for (int o = 16; o >= 1; o >>= 1) {
        z0 += __shfl_xor_sync(FULLM, z0, o);
        z1 += __shfl_xor_sync(FULLM, z1, o);
    }
    zout = head ? z1 : z0;
}

// ============ fused: aggregate layer1 + GEMM layer2 ================

__global__ void __launch_bounds__(256) k_aggmm2(const float* __restrict__ bias,
                                                const float* __restrict__ W,
                                                const float* __restrict__ as_,
                                                const float* __restrict__ ad_) {
    __shared__ __align__(16) float Ws[4096];
    __shared__ float xs[8][64];
    int t = threadIdx.x;
    {
        const float4* W4 = (const float4*)W;
        float4* w4 = (float4*)Ws;
        for (int i = t; i < 1024; i += 256) w4[i] = W4[i];
    }
    __syncthreads();
    int lane = t & 31, w = t >> 5;
    int head = lane >> 4;
    int warpsTotal = gridDim.x * 8;

    for (int node = blockIdx.x * 8 + w; node < NN; node += warpsTotal) {
        int beg = g_rowptr[node], end = g_rowptr[node + 1];
        float2 ad = g_adc1[node];
        float a0, a1, z;
        agg_node(g_asc1, g_hA, ad, beg, end, head, lane, a0, a1, z);
        float rz = 1.f / z;
        float r0 = fmaxf(a0 * rz + bias[2 * lane], 0.f);
        float r1 = fmaxf(a1 * rz + bias[2 * lane + 1], 0.f);
        xs[w][2 * lane]     = r0;
        xs[w][2 * lane + 1] = r1;
        __syncwarp();
        float o0 = 0.f, o1 = 0.f;
        #pragma unroll
        for (int k = 0; k < 64; k++) {
            float xv = xs[w][k];
            float2 wv = *(const float2*)(Ws + k * 64 + 2 * lane);
            o0 = fmaf(xv, wv.x, o0);
            o1 = fmaf(xv, wv.y, o1);
        }
        g_hC[node * 32 + lane] = __floats2half2_rn(o0, o1);
        float ps = o0 * as_[2 * lane] + o1 * as_[2 * lane + 1];
        float pd = o0 * ad_[2 * lane] + o1 * ad_[2 * lane + 1];
        #pragma unroll
        for (int o = 8; o >= 1; o >>= 1) {
            ps += __shfl_xor_sync(FULLM, ps, o);
            pd += __shfl_xor_sync(FULLM, pd, o);
        }
        float ps1 = __shfl_sync(FULLM, ps, 16);
        float pd1 = __shfl_sync(FULLM, pd, 16);
        if (lane == 0) {
            g_asc2[node] = make_float2(ps, ps1);
            g_adc2[node] = make_float2(pd, pd1);
        }
        __syncwarp();
    }
}

// ============ fused: aggregate layer2 + GEMM layer3 ================

__global__ void __launch_bounds__(256) k_aggmm3(const float* __restrict__ bias,
                                                const float* __restrict__ W,
                                                const float* __restrict__ as_,
                                                const float* __restrict__ ad_) {
    int t = threadIdx.x;
    int lane = t & 31, w = t >> 5;
    int head = lane >> 4;
    int warpsTotal = gridDim.x * 8;
    float4 w0 = ((const float4*)W)[2 * lane];
    float4 w1 = ((const float4*)W)[2 * lane + 1];
    float as0 = as_[0], as1 = as_[1], as2 = as_[2], as3 = as_[3];
    float ad0 = ad_[0], ad1 = ad_[1], ad2 = ad_[2], ad3 = ad_[3];

    for (int node = blockIdx.x * 8 + w; node < NN; node += warpsTotal) {
        int beg = g_rowptr[node], end = g_rowptr[node + 1];
        float2 ad = g_adc2[node];
        float a0, a1, z;
        agg_node(g_asc2, g_hC, ad, beg, end, head, lane, a0, a1, z);
        float rz = 1.f / z;
        float r0 = fmaxf(a0 * rz + bias[2 * lane], 0.f);
        float r1 = fmaxf(a1 * rz + bias[2 * lane + 1], 0.f);
        float4 acc;
        acc.x = r0 * w0.x + r1 * w1.x;
        acc.y = r0 * w0.y + r1 * w1.y;
        acc.z = r0 * w0.z + r1 * w1.z;
        acc.w = r0 * w0.w + r1 * w1.w;
        #pragma unroll
        for (int o = 16; o >= 1; o >>= 1) {
            acc.x += __shfl_xor_sync(FULLM, acc.x, o);
            acc.y += __shfl_xor_sync(FULLM, acc.y, o);
            acc.z += __shfl_xor_sync(FULLM, acc.z, o);
            acc.w += __shfl_xor_sync(FULLM, acc.w, o);
        }
        if (lane == 0) {
            g_h3[node] = acc;
            g_asc3[node] = acc.x * as0 + acc.y * as1 + acc.z * as2 + acc.w * as3;
            g_adc3[node] = acc.x * ad0 + acc.y * ad1 + acc.z * ad2 + acc.w * ad3;
        }
    }
}

// ===================== layer-3 aggregation + output ================

__global__ void __launch_bounds__(256) k_agg4(const float* __restrict__ bias,
                                              float4* __restrict__ out) {
    int t = threadIdx.x;
    int lane = t & 31, w = t >> 5;
    int warpsTotal = gridDim.x * 8;
    for (int node = blockIdx.x * 8 + w; node < NN; node += warpsTotal) {
        int beg = g_rowptr[node], end = g_rowptr[node + 1];
        float ad = g_adc3[node];
        float z = 0.f;
        float4 acc = make_float4(0.f, 0.f, 0.f, 0.f);
        #pragma unroll 2
        for (int i = beg + lane; i < end; i += 32) {
            int s = g_csr[i];
            float e = g_asc3[s] + ad;
            e = (e > 0.f) ? e : 0.2f * e;
            float ex = __expf(e);
            z += ex;
            float4 hv = g_h3[s];
            acc.x = fmaf(ex, hv.x, acc.x);
            acc.y = fmaf(ex, hv.y, acc.y);
            acc.z = fmaf(ex, hv.z, acc.z);
            acc.w = fmaf(ex, hv.w, acc.w);
        }
        #pragma unroll
        for (int o = 16; o >= 1; o >>= 1) {
            z     += __shfl_xor_sync(FULLM, z, o);
            acc.x += __shfl_xor_sync(FULLM, acc.x, o);
            acc.y += __shfl_xor_sync(FULLM, acc.y, o);
            acc.z += __shfl_xor_sync(FULLM, acc.z, o);
            acc.w += __shfl_xor_sync(FULLM, acc.w, o);
        }
        if (lane == 0) {
            float4 o4;
            o4.x = 100.f / (1.f + __expf(-(acc.x / z + bias[0])));
            o4.y = 100.f / (1.f + __expf(-(acc.y / z + bias[1])));
            o4.z = 100.f / (1.f + __expf(-(acc.z / z + bias[2])));
            o4.w = 100.f / (1.f + __expf(-(acc.w / z + bias[3])));
            out[node] = o4;
        }
    }
}

// ============================== launch =============================

extern "C" void kernel_launch(void* const* d_in, const int* in_sizes, int n_in,
                              void* d_out, int out_size) {
    const float* x   = (const float*)d_in[0];
    const int*   ei  = (const int*)d_in[1];
    const float* W1  = (const float*)d_in[2];
    const float* a1s = (const float*)d_in[3];
    const float* a1d = (const float*)d_in[4];
    const float* b1  = (const float*)d_in[5];
    const float* W2  = (const float*)d_in[6];
    const float* a2s = (const float*)d_in[7];
    const float* a2d = (const float*)d_in[8];
    const float* b2  = (const float*)d_in[9];
    const float* W3  = (const float*)d_in[10];
    const float* a3s = (const float*)d_in[11];
    const float* a3d = (const float*)d_in[12];
    const float* b3  = (const float*)d_in[13];
    float4* out = (float4*)d_out;

    int nb = (NN + 1023) / 1024;
    k_hist<<<(ETOT + 255) / 256, 256>>>(ei);       // g_cnt starts 0 (self-restoring)
    k_scan1<<<nb, 1024>>>();
    k_scan23<<<nb, 1024>>>();
    k_scatter<<<(ETOT + 255) / 256, 256>>>(ei);

    k_gemm1<<<AGG_GRID, 256>>>(x, W1, a1s, a1d);
    k_aggmm2<<<AGG_GRID, 256>>>(b1, W2, a2s, a2d);
    k_aggmm3<<<AGG_GRID, 256>>>(b2, W3, a3s, a3d);
    k_agg4<<<AGG_GRID, 256>>>(b3, out);
}

// round 4
// speedup vs baseline: 1.1665x; 1.1665x over previous
#include <cuda_runtime.h>
#include <cuda_fp16.h>

#define NN 100000
#define EE 3200000
#define ETOT (EE + NN)
#define AGG_GRID 1184
#define FULLM 0xffffffffu

// ---- device scratch ----
__device__ __half2 g_hA[NN * 32];
__device__ __half2 g_hC[NN * 32];
__device__ float2  g_asc1[NN], g_adc1[NN];
__device__ float2  g_asc2[NN], g_adc2[NN];
__device__ float   g_asc3[NN], g_adc3[NN];
__device__ float4  g_h3[NN];
__device__ int     g_cnt[NN];          // zero-init; scatter drains back to 0
__device__ int     g_rowptr[NN + 1];
__device__ int     g_csr[ETOT];
__device__ int     g_bsum[128];

// ============================ CSR build ============================

__global__ void k_hist(const int* __restrict__ ei) {
    int i = blockIdx.x * blockDim.x + threadIdx.x;
    if (i >= ETOT) return;
    int dst = (i < EE) ? ei[EE + i] : (i - EE);
    atomicAdd(&g_cnt[dst], 1);
}

__global__ void k_scan1() {
    __shared__ int sd[1024];
    int t = threadIdx.x;
    int i = blockIdx.x * 1024 + t;
    int v = (i < NN) ? g_cnt[i] : 0;
    sd[t] = v;
    __syncthreads();
    #pragma unroll
    for (int o = 1; o < 1024; o <<= 1) {
        int a = (t >= o) ? sd[t - o] : 0;
        __syncthreads();
        sd[t] += a;
        __syncthreads();
    }
    if (i < NN) g_rowptr[i] = sd[t] - v;
    if (t == 1023) g_bsum[blockIdx.x] = sd[1023];
}

__global__ void k_scan23() {
    __shared__ int off;
    int b = blockIdx.x, t = threadIdx.x;
    if (t < 32) {
        int acc = 0;
        for (int j = t; j < b; j += 32) acc += g_bsum[j];
        #pragma unroll
        for (int o = 16; o >= 1; o >>= 1) acc += __shfl_xor_sync(FULLM, acc, o);
        if (t == 0) off = acc;
    }
    __syncthreads();
    int i = b * 1024 + t;
    if (i < NN) g_rowptr[i] += off;
    if (b == gridDim.x - 1 && t == 0) g_rowptr[NN] = off + g_bsum[b];
}

__global__ void k_scatter(const int* __restrict__ ei) {
    int i = blockIdx.x * blockDim.x + threadIdx.x;
    if (i >= ETOT) return;
    int src, dst;
    if (i < EE) { src = ei[i]; dst = ei[EE + i]; }
    else        { src = i - EE; dst = i - EE; }
    int pos = atomicSub(&g_cnt[dst], 1) - 1;
    g_csr[g_rowptr[dst] + pos] = src;
}

// ======================= layer 1: GEMM + logits ====================

__global__ void __launch_bounds__(256) k_gemm1(const float* __restrict__ x,
                                               const float* __restrict__ W,
                                               const float* __restrict__ as_,
                                               const float* __restrict__ ad_) {
    __shared__ float Ws[640];
    int t = threadIdx.x;
    for (int i = t; i < 640; i += 256) Ws[i] = W[i];
    __syncthreads();
    int lane = t & 31, w = t >> 5;
    int warpsTotal = gridDim.x * 8;
    for (int node = blockIdx.x * 8 + w; node < NN; node += warpsTotal) {
        float a0 = 0.f, a1 = 0.f;
        #pragma unroll
        for (int k = 0; k < 10; k++) {
            float xv = x[node * 10 + k];
            a0 = fmaf(xv, Ws[k * 64 + 2 * lane], a0);
            a1 = fmaf(xv, Ws[k * 64 + 2 * lane + 1], a1);
        }
        g_hA[node * 32 + lane] = __floats2half2_rn(a0, a1);
        float ps = a0 * as_[2 * lane] + a1 * as_[2 * lane + 1];
        float pd = a0 * ad_[2 * lane] + a1 * ad_[2 * lane + 1];
        #pragma unroll
        for (int o = 8; o >= 1; o >>= 1) {
            ps += __shfl_xor_sync(FULLM, ps, o);
            pd += __shfl_xor_sync(FULLM, pd, o);
        }
        float ps1 = __shfl_sync(FULLM, ps, 16);
        float pd1 = __shfl_sync(FULLM, pd, 16);
        if (lane == 0) {
            g_asc1[node] = make_float2(ps, ps1);
            g_adc1[node] = make_float2(pd, pd1);
        }
    }
}

// ================= aggregation core (smem staged, MLP=8) ===========
// Warp per dst node. Per 32-edge chunk: stage src idx + exp(e) to smem,
// then consume with 8-deep explicit load batches so 8 gathers are in flight.

__device__ __forceinline__ void agg_node(const float2* __restrict__ asc,
                                         const __half2* __restrict__ feat,
                                         int* __restrict__ s_src,
                                         float2* __restrict__ s_ex,
                                         float2 ad, int beg, int end,
                                         int head, int lane,
                                         float& a0, float& a1, float& zout) {
    const float* exbase = ((const float*)s_ex) + head;
    float z0 = 0.f, z1 = 0.f;
    a0 = 0.f; a1 = 0.f;
    for (int cb = beg; cb < end; cb += 32) {
        int cnt = min(32, end - cb);
        float ex0 = 0.f, ex1 = 0.f;
        int s = 0;
        if (lane < cnt) {
            s = g_csr[cb + lane];
            float2 as = asc[s];
            float e0 = as.x + ad.x; e0 = (e0 > 0.f) ? e0 : 0.2f * e0;
            float e1 = as.y + ad.y; e1 = (e1 > 0.f) ? e1 : 0.2f * e1;
            ex0 = __expf(e0); ex1 = __expf(e1);
            z0 += ex0; z1 += ex1;
        }
        s_src[lane] = s;
        s_ex[lane]  = make_float2(ex0, ex1);
        __syncwarp();
        if (cnt == 32) {
            #pragma unroll
            for (int jb = 0; jb < 32; jb += 8) {
                float2 f[8]; float e[8];
                #pragma unroll
                for (int u = 0; u < 8; u++) {
                    int ss = s_src[jb + u];
                    e[u] = exbase[2 * (jb + u)];
                    f[u] = __half22float2(feat[ss * 32 + lane]);
                }
                #pragma unroll
                for (int u = 0; u < 8; u++) {
                    a0 = fmaf(e[u], f[u].x, a0);
                    a1 = fmaf(e[u], f[u].y, a1);
                }
            }
        } else {
            for (int j = 0; j < cnt; j++) {
                int ss = s_src[j];
                float exv = exbase[2 * j];
                float2 f = __half22float2(feat[ss * 32 + lane]);
                a0 = fmaf(exv, f.x, a0);
                a1 = fmaf(exv, f.y, a1);
            }
        }
        __syncwarp();
    }
    #pragma unroll
    for (int o = 16; o >= 1; o >>= 1) {
        z0 += __shfl_xor_sync(FULLM, z0, o);
        z1 += __shfl_xor_sync(FULLM, z1, o);
    }
    zout = head ? z1 : z0;
}

// ============ fused: aggregate layer1 + GEMM layer2 ================

__global__ void __launch_bounds__(256) k_aggmm2(const float* __restrict__ bias,
                                                const float* __restrict__ W,
                                                const float* __restrict__ as_,
                                                const float* __restrict__ ad_) {
    __shared__ __align__(16) float Ws[4096];
    __shared__ int    s_src[8][32];
    __shared__ float2 s_ex[8][32];
    __shared__ float  xs[8][64];
    int t = threadIdx.x;
    {
        const float4* W4 = (const float4*)W;
        float4* w4 = (float4*)Ws;
        for (int i = t; i < 1024; i += 256) w4[i] = W4[i];
    }
    __syncthreads();
    int lane = t & 31, w = t >> 5;
    int head = lane >> 4;
    int warpsTotal = gridDim.x * 8;

    for (int node = blockIdx.x * 8 + w; node < NN; node += warpsTotal) {
        int beg = g_rowptr[node], end = g_rowptr[node + 1];
        float2 ad = g_adc1[node];
        float a0, a1, z;
        agg_node(g_asc1, g_hA, s_src[w], s_ex[w], ad, beg, end, head, lane, a0, a1, z);
        float rz = 1.f / z;
        float r0 = fmaxf(a0 * rz + bias[2 * lane], 0.f);
        float r1 = fmaxf(a1 * rz + bias[2 * lane + 1], 0.f);
        xs[w][2 * lane]     = r0;
        xs[w][2 * lane + 1] = r1;
        __syncwarp();
        float o0 = 0.f, o1 = 0.f;
        #pragma unroll
        for (int k = 0; k < 64; k++) {
            float xv = xs[w][k];
            float2 wv = *(const float2*)(Ws + k * 64 + 2 * lane);
            o0 = fmaf(xv, wv.x, o0);
            o1 = fmaf(xv, wv.y, o1);
        }
        g_hC[node * 32 + lane] = __floats2half2_rn(o0, o1);
        float ps = o0 * as_[2 * lane] + o1 * as_[2 * lane + 1];
        float pd = o0 * ad_[2 * lane] + o1 * ad_[2 * lane + 1];
        #pragma unroll
        for (int o = 8; o >= 1; o >>= 1) {
            ps += __shfl_xor_sync(FULLM, ps, o);
            pd += __shfl_xor_sync(FULLM, pd, o);
        }
        float ps1 = __shfl_sync(FULLM, ps, 16);
        float pd1 = __shfl_sync(FULLM, pd, 16);
        if (lane == 0) {
            g_asc2[node] = make_float2(ps, ps1);
            g_adc2[node] = make_float2(pd, pd1);
        }
        __syncwarp();
    }
}

// ============ fused: aggregate layer2 + GEMM layer3 ================

__global__ void __launch_bounds__(256) k_aggmm3(const float* __restrict__ bias,
                                                const float* __restrict__ W,
                                                const float* __restrict__ as_,
                                                const float* __restrict__ ad_) {
    __shared__ int    s_src[8][32];
    __shared__ float2 s_ex[8][32];
    int t = threadIdx.x;
    int lane = t & 31, w = t >> 5;
    int head = lane >> 4;
    int warpsTotal = gridDim.x * 8;
    float4 w0 = ((const float4*)W)[2 * lane];
    float4 w1 = ((const float4*)W)[2 * lane + 1];
    float as0 = as_[0], as1 = as_[1], as2 = as_[2], as3 = as_[3];
    float ad0 = ad_[0], ad1 = ad_[1], ad2 = ad_[2], ad3 = ad_[3];

    for (int node = blockIdx.x * 8 + w; node < NN; node += warpsTotal) {
        int beg = g_rowptr[node], end = g_rowptr[node + 1];
        float2 ad = g_adc2[node];
        float a0, a1, z;
        agg_node(g_asc2, g_hC, s_src[w], s_ex[w], ad, beg, end, head, lane, a0, a1, z);
        float rz = 1.f / z;
        float r0 = fmaxf(a0 * rz + bias[2 * lane], 0.f);
        float r1 = fmaxf(a1 * rz + bias[2 * lane + 1], 0.f);
        float4 acc;
        acc.x = r0 * w0.x + r1 * w1.x;
        acc.y = r0 * w0.y + r1 * w1.y;
        acc.z = r0 * w0.z + r1 * w1.z;
        acc.w = r0 * w0.w + r1 * w1.w;
        #pragma unroll
        for (int o = 16; o >= 1; o >>= 1) {
            acc.x += __shfl_xor_sync(FULLM, acc.x, o);
            acc.y += __shfl_xor_sync(FULLM, acc.y, o);
            acc.z += __shfl_xor_sync(FULLM, acc.z, o);
            acc.w += __shfl_xor_sync(FULLM, acc.w, o);
        }
        if (lane == 0) {
            g_h3[node] = acc;
            g_asc3[node] = acc.x * as0 + acc.y * as1 + acc.z * as2 + acc.w * as3;
            g_adc3[node] = acc.x * ad0 + acc.y * ad1 + acc.z * ad2 + acc.w * ad3;
        }
    }
}

// ===================== layer-3 aggregation + output ================

__global__ void __launch_bounds__(256) k_agg4(const float* __restrict__ bias,
                                              float4* __restrict__ out) {
    int t = threadIdx.x;
    int lane = t & 31, w = t >> 5;
    int warpsTotal = gridDim.x * 8;
    for (int node = blockIdx.x * 8 + w; node < NN; node += warpsTotal) {
        int beg = g_rowptr[node], end = g_rowptr[node + 1];
        float ad = g_adc3[node];
        float z = 0.f;
        float4 acc = make_float4(0.f, 0.f, 0.f, 0.f);
        #pragma unroll 2
        for (int i = beg + lane; i < end; i += 32) {
            int s = g_csr[i];
            float e = g_asc3[s] + ad;
            e = (e > 0.f) ? e : 0.2f * e;
            float ex = __expf(e);
            z += ex;
            float4 hv = g_h3[s];
            acc.x = fmaf(ex, hv.x, acc.x);
            acc.y = fmaf(ex, hv.y, acc.y);
            acc.z = fmaf(ex, hv.z, acc.z);
            acc.w = fmaf(ex, hv.w, acc.w);
        }
        #pragma unroll
        for (int o = 16; o >= 1; o >>= 1) {
            z     += __shfl_xor_sync(FULLM, z, o);
            acc.x += __shfl_xor_sync(FULLM, acc.x, o);
            acc.y += __shfl_xor_sync(FULLM, acc.y, o);
            acc.z += __shfl_xor_sync(FULLM, acc.z, o);
            acc.w += __shfl_xor_sync(FULLM, acc.w, o);
        }
        if (lane == 0) {
            float4 o4;
            o4.x = 100.f / (1.f + __expf(-(acc.x / z + bias[0])));
            o4.y = 100.f / (1.f + __expf(-(acc.y / z + bias[1])));
            o4.z = 100.f / (1.f + __expf(-(acc.z / z + bias[2])));
            o4.w = 100.f / (1.f + __expf(-(acc.w / z + bias[3])));
            out[node] = o4;
        }
    }
}

// ============================== launch =============================

extern "C" void kernel_launch(void* const* d_in, const int* in_sizes, int n_in,
                              void* d_out, int out_size) {
    const float* x   = (const float*)d_in[0];
    const int*   ei  = (const int*)d_in[1];
    const float* W1  = (const float*)d_in[2];
    const float* a1s = (const float*)d_in[3];
    const float* a1d = (const float*)d_in[4];
    const float* b1  = (const float*)d_in[5];
    const float* W2  = (const float*)d_in[6];
    const float* a2s = (const float*)d_in[7];
    const float* a2d = (const float*)d_in[8];
    const float* b2  = (const float*)d_in[9];
    const float* W3  = (const float*)d_in[10];
    const float* a3s = (const float*)d_in[11];
    const float* a3d = (const float*)d_in[12];
    const float* b3  = (const float*)d_in[13];
    float4* out = (float4*)d_out;

    int nb = (NN + 1023) / 1024;
    k_hist<<<(ETOT + 255) / 256, 256>>>(ei);
    k_scan1<<<nb, 1024>>>();
    k_scan23<<<nb, 1024>>>();
    k_scatter<<<(ETOT + 255) / 256, 256>>>(ei);

    k_gemm1<<<AGG_GRID, 256>>>(x, W1, a1s, a1d);
    k_aggmm2<<<AGG_GRID, 256>>>(b1, W2, a2s, a2d);
    k_aggmm3<<<AGG_GRID, 256>>>(b2, W3, a3s, a3d);
    k_agg4<<<AGG_GRID, 256>>>(b3, out);
}